// round 1
// baseline (speedup 1.0000x reference)
#include <cuda_runtime.h>

#define NBATCH 2048
#define CDIM   256
#define HW     49     // 7*7 spatial positions
#define QP     56     // q padded to 56 for f32x2 pairs / alignment
#define KC     16     // channel chunk resident in smem
#define NB     4      // batches per CTA
#define NT     224    // 7 warps; 4*49=196 compute threads

// ---- packed fp32x2 helpers (sm_100+ PTX) ----
__device__ __forceinline__ unsigned long long dup_f32x2(float x) {
    unsigned long long r;
    asm("mov.b64 %0, {%1, %1};" : "=l"(r) : "f"(x));
    return r;
}
__device__ __forceinline__ unsigned long long pack_f32x2(float lo, float hi) {
    unsigned long long r;
    asm("mov.b64 %0, {%1, %2};" : "=l"(r) : "f"(lo), "f"(hi));
    return r;
}
__device__ __forceinline__ void fma_f32x2(unsigned long long &d,
                                          unsigned long long a,
                                          unsigned long long b) {
    asm("fma.rn.f32x2 %0, %1, %2, %0;" : "+l"(d) : "l"(a), "l"(b));
}
__device__ __forceinline__ void unpack_f32x2(unsigned long long v, float &lo, float &hi) {
    asm("mov.b64 {%0, %1}, %2;" : "=f"(lo), "=f"(hi) : "l"(v));
}

__global__ __launch_bounds__(NT, 2) void pixpro_kernel(
    const float* __restrict__ baseF,   // [B, C, 49]
    const float* __restrict__ momF,    // [B, C, 49]
    const int*   __restrict__ baseA,   // [49*49]  (p*49+q)
    const int*   __restrict__ momA,    // [49*49]
    float*       __restrict__ out)     // [B]
{
    __shared__ __align__(16) float As[NB * KC * HW]; // [nb][k][p]
    __shared__ __align__(16) float Bs[NB * KC * QP]; // [nb][k][q] (q padded)
    __shared__ float snA[NB][HW];
    __shared__ float snB[NB][QP];
    __shared__ float red[NT];

    const int tid  = threadIdx.x;
    const int bloc = tid / HW;            // 0..3 compute, 4 = helper-only
    const int s    = tid - bloc * HW;
    const int ty   = s / 7;               // p-group
    const int tx   = s - ty * 7;          // q-group
    const bool active = (bloc < NB);
    const int b0 = blockIdx.x * NB;

    unsigned long long acc[7][4];
    #pragma unroll
    for (int r = 0; r < 7; ++r)
        #pragma unroll
        for (int u = 0; u < 4; ++u) acc[r][u] = 0ULL;

    float na[7] = {0.f,0.f,0.f,0.f,0.f,0.f,0.f};   // |a|^2 partials (tx==0 threads)
    unsigned long long nb2[4] = {0ULL,0ULL,0ULL,0ULL}; // |b|^2 packed (ty==0 threads)

    const float* aBase = &As[(active ? bloc : 0) * KC * HW + ty];
    const float* bBase = &Bs[(active ? bloc : 0) * KC * QP + tx * 8];

    for (int k0 = 0; k0 < CDIM; k0 += KC) {
        __syncthreads();   // protect smem from previous chunk's readers
        // ---- load A (base) chunk: NB*KC*49 floats, contiguous per batch, float4 ----
        {
            const int n4 = NB * KC * HW / 4;           // 784
            float4* dst = (float4*)As;
            #pragma unroll 2
            for (int i = tid; i < n4; i += NT) {
                int bb = i / (KC * HW / 4);
                int r4 = i - bb * (KC * HW / 4);
                const float4* src =
                    (const float4*)(baseF + ((b0 + bb) * CDIM + k0) * HW);
                dst[i] = src[r4];
            }
        }
        // ---- load B (moment) chunk: scatter into QP-stride rows ----
        {
            const int n = NB * KC * HW;                // 3136
            #pragma unroll 2
            for (int i = tid; i < n; i += NT) {
                int bb = i / (KC * HW);
                int r  = i - bb * (KC * HW);
                int kk = r / HW;
                int q  = r - kk * HW;
                Bs[(bb * KC + kk) * QP + q] =
                    momF[((b0 + bb) * CDIM + k0) * HW + r];
            }
        }
        __syncthreads();

        if (active) {
            #pragma unroll 4
            for (int k = 0; k < KC; ++k) {
                const float* arow = aBase + k * HW;
                const float* brow = bBase + k * QP;
                unsigned long long bb4[4];
                #pragma unroll
                for (int u = 0; u < 4; ++u) {
                    float2 t = *(const float2*)(brow + 2 * u);
                    bb4[u] = pack_f32x2(t.x, t.y);
                }
                if (ty == 0) {
                    #pragma unroll
                    for (int u = 0; u < 4; ++u) fma_f32x2(nb2[u], bb4[u], bb4[u]);
                }
                #pragma unroll
                for (int r = 0; r < 7; ++r) {
                    float av = arow[7 * r];
                    if (tx == 0) na[r] = fmaf(av, av, na[r]);
                    unsigned long long ap = dup_f32x2(av);
                    #pragma unroll
                    for (int u = 0; u < 4; ++u) fma_f32x2(acc[r][u], ap, bb4[u]);
                }
            }
        }
    }

    // ---- norms^2 to smem ----
    if (active && tx == 0) {
        #pragma unroll
        for (int r = 0; r < 7; ++r) snA[bloc][ty + 7 * r] = na[r];
    }
    if (active && ty == 0) {
        #pragma unroll
        for (int u = 0; u < 4; ++u) {
            float lo, hi; unpack_f32x2(nb2[u], lo, hi);
            snB[bloc][tx * 8 + 2 * u]     = lo;
            snB[bloc][tx * 8 + 2 * u + 1] = hi;
        }
    }
    __syncthreads();

    // ---- epilogue: masked weighted sum of cos ----
    float part = 0.f;
    if (active) {
        #pragma unroll
        for (int r = 0; r < 7; ++r) {
            int p = ty + 7 * r;
            float np = sqrtf(snA[bloc][p]);
            #pragma unroll
            for (int u = 0; u < 4; ++u) {
                float lo, hi; unpack_f32x2(acc[r][u], lo, hi);
                int q0 = tx * 8 + 2 * u;
                if (q0 < HW) {
                    float nq = sqrtf(snB[bloc][q0]);
                    float w = (float)(baseA[p * HW + q0] == 1)
                            + (float)(momA[q0 * HW + p] == 1);
                    part += w * lo / fmaxf(np * nq, 1e-6f);
                }
                if (q0 + 1 < HW) {
                    float nq = sqrtf(snB[bloc][q0 + 1]);
                    float w = (float)(baseA[p * HW + q0 + 1] == 1)
                            + (float)(momA[(q0 + 1) * HW + p] == 1);
                    part += w * hi / fmaxf(np * nq, 1e-6f);
                }
            }
        }
    }
    red[tid] = part;
    __syncthreads();
    if (active && s == 0) {
        float tot = 0.f;
        #pragma unroll 7
        for (int i = 0; i < HW; ++i) tot += red[bloc * HW + i];
        out[b0 + bloc] = -tot * (1.0f / 2401.0f);
    }
}

extern "C" void kernel_launch(void* const* d_in, const int* in_sizes, int n_in,
                              void* d_out, int out_size) {
    const float* baseF = (const float*)d_in[0];
    const float* momF  = (const float*)d_in[1];
    const int*   baseA = (const int*)d_in[2];
    const int*   momA  = (const int*)d_in[3];
    float* out = (float*)d_out;
    (void)in_sizes; (void)n_in; (void)out_size;

    pixpro_kernel<<<NBATCH / NB, NT>>>(baseF, momF, baseA, momA, out);
}

// round 2
// speedup vs baseline: 1.8073x; 1.8073x over previous
#include <cuda_runtime.h>
#include <cstdint>

#define NBATCH 2048
#define CDIM   256
#define HW     49
#define QP     56            // q padded for 8B-aligned paired loads
#define KC     16            // channels per smem chunk
#define NB     4             // batches per CTA
#define NT     224           // 7 warps
#define NCHUNK (CDIM / KC)   // 16
#define A_CH   (NB * KC * HW)   // 3136 floats per buffer
#define B_CH   (NB * KC * QP)   // 3584 floats per buffer
#define SMEM_DYN ((2 * A_CH + 2 * B_CH) * 4)  // 53760 B

typedef unsigned long long ull;

// ---- packed fp32x2 helpers ----
__device__ __forceinline__ ull dup_f32x2(float x) {
    ull r; asm("mov.b64 %0, {%1, %1};" : "=l"(r) : "f"(x)); return r;
}
__device__ __forceinline__ void fma_f32x2(ull &d, ull a, ull b) {
    asm("fma.rn.f32x2 %0, %1, %2, %0;" : "+l"(d) : "l"(a), "l"(b));
}
__device__ __forceinline__ void unpack_f32x2(ull v, float &lo, float &hi) {
    asm("mov.b64 {%0, %1}, %2;" : "=f"(lo), "=f"(hi) : "l"(v));
}

// ---- cp.async ----
__device__ __forceinline__ void cp16(uint32_t d, const void* s) {
    asm volatile("cp.async.cg.shared.global [%0], [%1], 16;" :: "r"(d), "l"(s));
}
__device__ __forceinline__ void cp4(uint32_t d, const void* s) {
    asm volatile("cp.async.ca.shared.global [%0], [%1], 4;" :: "r"(d), "l"(s));
}
__device__ __forceinline__ void cp_commit() { asm volatile("cp.async.commit_group;"); }
__device__ __forceinline__ void cp_wait1()  { asm volatile("cp.async.wait_group 1;"); }
__device__ __forceinline__ void cp_wait0()  { asm volatile("cp.async.wait_group 0;"); }

__global__ __launch_bounds__(NT, 2) void pixpro_kernel(
    const float* __restrict__ baseF,   // [B, C, 49]
    const float* __restrict__ momF,    // [B, C, 49]
    const int*   __restrict__ baseA,   // [49*49]  (p*49+q)
    const int*   __restrict__ momA,    // [49*49]
    float*       __restrict__ out)     // [B]
{
    extern __shared__ __align__(16) float sm[];
    float* As = sm;                    // 2 buffers of [nb][k][p] (stride HW)
    float* Bs = sm + 2 * A_CH;         // 2 buffers of [nb][k][q] (stride QP)

    __shared__ float snA[NB][HW];
    __shared__ float snB[NB][HW];
    __shared__ float red[NT];

    const int tid  = threadIdx.x;
    const int bloc = tid / HW;
    const int s    = tid - bloc * HW;
    const int ty   = s / 7;
    const int tx   = s - ty * 7;
    const bool active = (bloc < NB);
    const int b0 = blockIdx.x * NB;

    const uint32_t AsSM = (uint32_t)__cvta_generic_to_shared(As);
    const uint32_t BsSM = (uint32_t)__cvta_generic_to_shared(Bs);
    const float4* baseF4 = (const float4*)(baseF + (size_t)b0 * CDIM * HW);
    const float*  momB   = momF + (size_t)b0 * CDIM * HW;

    // ---- chunk loader: issues cp.async for chunk c into buffer buf ----
    auto issue_chunk = [&](int c, int buf) {
        // A: 784 float4s (contiguous per batch)
        uint32_t aDst = AsSM + buf * (A_CH * 4);
        #pragma unroll
        for (int j = 0; j < 4; ++j) {
            int i4 = tid + j * NT;
            if (j < 3 || i4 < A_CH / 4) {
                int bb = i4 / 196;                      // 196 = KC*HW/4
                cp16(aDst + i4 * 16,
                     baseF4 + (c * 196 + i4 + bb * 2940)); // 2940=(CDIM-KC)*HW/4
            }
        }
        // B: 3136 floats scattered into QP-stride rows
        uint32_t bDst = BsSM + buf * (B_CH * 4);
        #pragma unroll
        for (int j = 0; j < 14; ++j) {
            int i  = tid + j * NT;
            int kl = i / 49;                            // linear (bb*KC+kk)
            int bb = kl >> 4;
            cp4(bDst + (i + 7 * kl) * 4,
                momB + c * (KC * HW) + i + bb * 11760); // 11760=(CDIM-KC)*HW
        }
        cp_commit();
    };

    ull acc[7][4];
    #pragma unroll
    for (int r = 0; r < 7; ++r)
        #pragma unroll
        for (int u = 0; u < 4; ++u) acc[r][u] = 0ULL;
    float n0 = 0.f, n1 = 0.f;  // norm^2 accumulators (separate task mapping)

    issue_chunk(0, 0);
    issue_chunk(1, 1);

    for (int c = 0; c < NCHUNK; ++c) {
        const int buf = c & 1;
        if (c == NCHUNK - 1) cp_wait0(); else cp_wait1();
        __syncthreads();

        // ---- gram accumulation ----
        if (active) {
            const float* Ab = As + buf * A_CH + bloc * (KC * HW) + ty;
            const float* Bb = Bs + buf * B_CH + bloc * (KC * QP) + tx * 8;
            #pragma unroll 4
            for (int k = 0; k < KC; ++k) {
                const float* ar = Ab + k * HW;
                const ull*   bp = (const ull*)(Bb + k * QP);
                ull bb4[4];
                #pragma unroll
                for (int u = 0; u < 4; ++u) bb4[u] = bp[u];
                #pragma unroll
                for (int r = 0; r < 7; ++r) {
                    ull ap = dup_f32x2(ar[7 * r]);
                    #pragma unroll
                    for (int u = 0; u < 4; ++u) fma_f32x2(acc[r][u], ap, bb4[u]);
                }
            }
        }

        // ---- norms from resident smem (392 tasks over 224 threads) ----
        {
            const float* src; int st;
            if (tid < 196) { src = As + buf * A_CH + (tid / 49) * (KC * HW) + (tid % 49); st = HW; }
            else { int w = tid - 196; src = Bs + buf * B_CH + (w / 49) * (KC * QP) + (w % 49); st = QP; }
            #pragma unroll
            for (int k = 0; k < KC; ++k) { float v = src[k * st]; n0 = fmaf(v, v, n0); }
        }
        if (tid < 168) {
            int w = tid + 28;  // b-norm positions 28..195
            const float* src = Bs + buf * B_CH + (w / 49) * (KC * QP) + (w % 49);
            #pragma unroll
            for (int k = 0; k < KC; ++k) { float v = src[k * QP]; n1 = fmaf(v, v, n1); }
        }

        __syncthreads();   // everyone done reading buf before cp.async overwrites it
        if (c + 2 < NCHUNK) issue_chunk(c + 2, buf);
    }

    // ---- publish norms^2 ----
    if (tid < 196) snA[tid / 49][tid % 49] = n0;
    else { int w = tid - 196; snB[w / 49][w % 49] = n0; }
    if (tid < 168) { int w = tid + 28; snB[w / 49][w % 49] = n1; }
    __syncthreads();

    // ---- epilogue: masked weighted sum of cos ----
    float part = 0.f;
    if (active) {
        #pragma unroll
        for (int r = 0; r < 7; ++r) {
            int p = ty + 7 * r;
            float np = sqrtf(snA[bloc][p]);
            #pragma unroll
            for (int u = 0; u < 4; ++u) {
                float lo, hi; unpack_f32x2(acc[r][u], lo, hi);
                int q0 = tx * 8 + 2 * u;
                if (q0 < HW) {
                    float nq = sqrtf(snB[bloc][q0]);
                    float w = (float)(baseA[p * HW + q0] == 1)
                            + (float)(momA[q0 * HW + p] == 1);
                    part += w * lo / fmaxf(np * nq, 1e-6f);
                }
                if (q0 + 1 < HW) {
                    float nq = sqrtf(snB[bloc][q0 + 1]);
                    float w = (float)(baseA[p * HW + q0 + 1] == 1)
                            + (float)(momA[(q0 + 1) * HW + p] == 1);
                    part += w * hi / fmaxf(np * nq, 1e-6f);
                }
            }
        }
    }
    red[tid] = part;
    __syncthreads();
    if (active && s == 0) {
        float tot = 0.f;
        #pragma unroll 7
        for (int i = 0; i < HW; ++i) tot += red[bloc * HW + i];
        out[b0 + bloc] = -tot * (1.0f / 2401.0f);
    }
}

extern "C" void kernel_launch(void* const* d_in, const int* in_sizes, int n_in,
                              void* d_out, int out_size) {
    const float* baseF = (const float*)d_in[0];
    const float* momF  = (const float*)d_in[1];
    const int*   baseA = (const int*)d_in[2];
    const int*   momA  = (const int*)d_in[3];
    float* out = (float*)d_out;
    (void)in_sizes; (void)n_in; (void)out_size;

    cudaFuncSetAttribute(pixpro_kernel,
                         cudaFuncAttributeMaxDynamicSharedMemorySize, SMEM_DYN);
    pixpro_kernel<<<NBATCH / NB, NT, SMEM_DYN>>>(baseF, momF, baseA, momA, out);
}

// round 4
// speedup vs baseline: 2.0742x; 1.1476x over previous
#include <cuda_runtime.h>
#include <cstdint>

#define HW      49
#define CDIM    256
#define NTHR    256
#define NB      2              // batches per CTA
#define GRID    1024           // 1024 * 2 = 2048 batches
#define KC      8              // channels per chunk (one k8 MMA step)
#define NCHUNK  32
#define SBUF    4608           // floats per buffer: 2 batches * (A 1152 + B 1152)
#define WM_OFF  (2 * SBUF)     // 9216: combined mask, 2401 floats (pad 2432)
#define SN_OFF  (WM_OFF + 2432)
#define DYN_FLOATS (SN_OFF + 256)   // snorm: 4 groups * 64
#define NELEM   1568           // staged elements per chunk: 2b*2t*8ch*49p

__device__ __forceinline__ uint32_t cvt_tf32(float x) {
    uint32_t r; asm("cvt.rna.tf32.f32 %0, %1;" : "=r"(r) : "f"(x)); return r;
}
__device__ __forceinline__ void mma8(float* d, const uint32_t* a, const uint32_t* b) {
    asm("mma.sync.aligned.m16n8k8.row.col.f32.tf32.tf32.f32 "
        "{%0,%1,%2,%3}, {%4,%5,%6,%7}, {%8,%9}, {%0,%1,%2,%3};"
        : "+f"(d[0]), "+f"(d[1]), "+f"(d[2]), "+f"(d[3])
        : "r"(a[0]), "r"(a[1]), "r"(a[2]), "r"(a[3]), "r"(b[0]), "r"(b[1]));
}

__global__ __launch_bounds__(NTHR, 2) void pixpro_mma(
    const float* __restrict__ baseF,   // [B, 256, 49]
    const float* __restrict__ momF,    // [B, 256, 49]
    const int*   __restrict__ baseA,   // [49*49]  (p*49+q)
    const int*   __restrict__ momA,    // [49*49]
    float*       __restrict__ out)     // [B]
{
    extern __shared__ float sm[];
    __shared__ float wsum[8];

    const int tid  = threadIdx.x;
    const int wid  = tid >> 5;
    const int lane = tid & 31;
    const int b0   = blockIdx.x * NB;

    // ---- init: combined mask (float) + norm accumulators ----
    for (int i = tid; i < HW * HW; i += NTHR) {
        int p = i / HW, q = i - p * HW;
        sm[WM_OFF + i] = (float)((baseA[i] == 1) + (momA[q * HW + p] == 1));
    }
    for (int i = tid; i < 256; i += NTHR) sm[SN_OFF + i] = 0.f;

    // ---- per-thread staging descriptors (fixed across chunks) ----
    uint32_t off[7], dst[7];
    float    accn[7];
    #pragma unroll
    for (int j = 0; j < 7; ++j) {
        accn[j] = 0.f;
        int i = tid + j * NTHR;
        if (i < NELEM) {
            int g  = i / 392;           // bit0 = tensor, bit1 = batch
            int bb = g >> 1, t = g & 1;
            int r  = i - g * 392;
            int ch = r / 49, p = r - ch * 49;
            off[j] = (uint32_t)((b0 + bb) * (CDIM * HW) + r) | (t ? 0x80000000u : 0u);
            dst[j] = bb * 2304 + t * 1152 + ch * 72 + p;
        }
    }

    // ---- prologue: stage chunk 0 into buffer 0 ----
    {
        float v[7];
        #pragma unroll
        for (int j = 0; j < 7; ++j)
            if (j < 6 || tid < (NELEM - 6 * NTHR)) {
                uint32_t o = off[j];
                const float* sp = (o & 0x80000000u) ? momF : baseF;
                v[j] = __ldg(sp + (o & 0x7FFFFFFFu));
            }
        #pragma unroll
        for (int j = 0; j < 7; ++j)
            if (j < 6 || tid < (NELEM - 6 * NTHR)) {
                uint32_t hb = cvt_tf32(v[j]);
                float hv = __uint_as_float(hb);
                sm[dst[j]]       = hv;
                sm[dst[j] + 576] = __uint_as_float(cvt_tf32(v[j] - hv));
                accn[j] = fmaf(v[j], v[j], accn[j]);
            }
    }

    // ---- main loop ----
    const int bb    = wid >> 2;           // batch within CTA
    const int mbase = (wid & 3) * 16;     // m16 tile row base
    float acc[7][4];
    #pragma unroll
    for (int nt = 0; nt < 7; ++nt)
        #pragma unroll
        for (int u = 0; u < 4; ++u) acc[nt][u] = 0.f;

    const uint32_t* smu = (const uint32_t*)sm;

    for (int c = 0; c < NCHUNK; ++c) {
        __syncthreads();

        // issue LDG for chunk c+1 (latency hidden under MMAs below)
        float v[7];
        if (c + 1 < NCHUNK) {
            #pragma unroll
            for (int j = 0; j < 7; ++j)
                if (j < 6 || tid < (NELEM - 6 * NTHR)) {
                    uint32_t o = off[j];
                    const float* sp = (o & 0x80000000u) ? momF : baseF;
                    v[j] = __ldg(sp + (o & 0x7FFFFFFFu) + (c + 1) * 392);
                }
        }

        // ---- MMAs on buffer c&1 ----
        {
            const int abase = (c & 1) * SBUF + bb * 2304;
            const int bbase = abase + 1152;
            const int kq = lane & 3, gq = lane >> 2;

            uint32_t afr[2][4];
            #pragma unroll
            for (int s = 0; s < 2; ++s) {
                int a0 = abase + (s * 8 + kq) * 72 + mbase + gq;
                afr[s][0] = smu[a0];
                afr[s][1] = smu[a0 + 8];
                afr[s][2] = smu[a0 + 4 * 72];
                afr[s][3] = smu[a0 + 4 * 72 + 8];
            }
            #pragma unroll
            for (int nt = 0; nt < 7; ++nt) {
                uint32_t bh[2], bl[2];
                int bh0 = bbase + kq * 72 + nt * 8 + gq;
                bh[0] = smu[bh0];
                bh[1] = smu[bh0 + 4 * 72];
                int bl0 = bh0 + 8 * 72;
                bl[0] = smu[bl0];
                bl[1] = smu[bl0 + 4 * 72];
                mma8(acc[nt], afr[0], bh);   // hi * hi
                mma8(acc[nt], afr[0], bl);   // hi * lo
                mma8(acc[nt], afr[1], bh);   // lo * hi
            }
        }

        // ---- split + STS chunk c+1 into the other buffer ----
        if (c + 1 < NCHUNK) {
            float* dbuf = sm + ((c + 1) & 1) * SBUF;
            #pragma unroll
            for (int j = 0; j < 7; ++j)
                if (j < 6 || tid < (NELEM - 6 * NTHR)) {
                    uint32_t hb = cvt_tf32(v[j]);
                    float hv = __uint_as_float(hb);
                    dbuf[dst[j]]       = hv;
                    dbuf[dst[j] + 576] = __uint_as_float(cvt_tf32(v[j] - hv));
                    accn[j] = fmaf(v[j], v[j], accn[j]);
                }
        }
    }

    // ---- flush norm partials ----
    #pragma unroll
    for (int j = 0; j < 7; ++j) {
        int i = tid + j * NTHR;
        if (i < NELEM) {
            int g = i / 392;
            int p = (i - g * 392) % 49;
            atomicAdd(&sm[SN_OFF + g * 64 + p], accn[j]);
        }
    }
    __syncthreads();
    if (tid < 4 * HW) {
        int g = tid / HW, p = tid - g * HW;
        sm[SN_OFF + g * 64 + p] = rsqrtf(sm[SN_OFF + g * 64 + p]);
    }
    __syncthreads();

    // ---- epilogue: mask + norms + reduce ----
    {
        const float* invP = sm + SN_OFF + (bb * 2 + 0) * 64;  // base norms
        const float* invQ = sm + SN_OFF + (bb * 2 + 1) * 64;  // moment norms
        const float* wm   = sm + WM_OFF;
        const int r0 = mbase + (lane >> 2);
        const int r1 = r0 + 8;
        const int c0 = (lane & 3) * 2;
        const bool v0 = r0 < HW, v1 = r1 < HW;
        const float ip0 = v0 ? invP[r0] : 0.f;
        const float ip1 = v1 ? invP[r1] : 0.f;
        float part = 0.f;
        #pragma unroll
        for (int nt = 0; nt < 7; ++nt) {
            int q0 = nt * 8 + c0;
            int q1 = q0 + 1;
            if (q0 < HW) {
                float iq = invQ[q0];
                if (v0) part = fmaf(acc[nt][0], wm[r0 * HW + q0] * ip0 * iq, part);
                if (v1) part = fmaf(acc[nt][2], wm[r1 * HW + q0] * ip1 * iq, part);
            }
            if (q1 < HW) {
                float iq = invQ[q1];
                if (v0) part = fmaf(acc[nt][1], wm[r0 * HW + q1] * ip0 * iq, part);
                if (v1) part = fmaf(acc[nt][3], wm[r1 * HW + q1] * ip1 * iq, part);
            }
        }
        #pragma unroll
        for (int o = 16; o; o >>= 1) part += __shfl_xor_sync(0xFFFFFFFFu, part, o);
        if (lane == 0) wsum[wid] = part;
    }
    __syncthreads();
    if (tid < NB) {
        float t = wsum[tid * 4] + wsum[tid * 4 + 1] + wsum[tid * 4 + 2] + wsum[tid * 4 + 3];
        out[b0 + tid] = -t * (1.0f / 2401.0f);
    }
}

extern "C" void kernel_launch(void* const* d_in, const int* in_sizes, int n_in,
                              void* d_out, int out_size) {
    const float* baseF = (const float*)d_in[0];
    const float* momF  = (const float*)d_in[1];
    const int*   baseA = (const int*)d_in[2];
    const int*   momA  = (const int*)d_in[3];
    float* out = (float*)d_out;
    (void)in_sizes; (void)n_in; (void)out_size;

    const int dynBytes = DYN_FLOATS * 4;
    cudaFuncSetAttribute(pixpro_mma, cudaFuncAttributeMaxDynamicSharedMemorySize, dynBytes);
    pixpro_mma<<<GRID, NTHR, dynBytes>>>(baseF, momF, baseA, momA, out);
}

// round 5
// speedup vs baseline: 3.2014x; 1.5435x over previous
#include <cuda_runtime.h>
#include <cstdint>

#define HW      49
#define CDIM    256
#define NTHR    256
#define NB      2              // batches per CTA
#define GRID    1024
#define NCHUNK  16             // 16 channels per chunk
#define BUFW    4096           // words per buffer: 2 batches * 2048
#define WM_OFF  8192           // combined mask (float), 2401 (pad 2432)
#define SN_OFF  (WM_OFF + 2432)
#define DYN_WORDS (SN_OFF + 256)
#define NPAIR   1568           // channel-pairs staged per chunk (2b*2t*8kp*49)

// pack two fp32 -> bf16x2 word: lower 16 = even channel, upper 16 = odd channel
__device__ __forceinline__ uint32_t bf16pack(float even, float odd) {
    uint32_t r;
    asm("cvt.rn.bf16x2.f32 %0, %1, %2;" : "=r"(r) : "f"(odd), "f"(even));
    return r;
}
__device__ __forceinline__ void mma16(float* d, const uint32_t* a,
                                      uint32_t b0, uint32_t b1) {
    asm("mma.sync.aligned.m16n8k16.row.col.f32.bf16.bf16.f32 "
        "{%0,%1,%2,%3}, {%4,%5,%6,%7}, {%8,%9}, {%0,%1,%2,%3};"
        : "+f"(d[0]), "+f"(d[1]), "+f"(d[2]), "+f"(d[3])
        : "r"(a[0]), "r"(a[1]), "r"(a[2]), "r"(a[3]), "r"(b0), "r"(b1));
}

__global__ __launch_bounds__(NTHR, 2) void pixpro_bf16(
    const float* __restrict__ baseF,   // [B, 256, 49]
    const float* __restrict__ momF,    // [B, 256, 49]
    const int*   __restrict__ baseA,   // [49*49] (p*49+q)
    const int*   __restrict__ momA,    // [49*49]
    float*       __restrict__ out)     // [B]
{
    extern __shared__ float sm[];
    uint32_t* smw = (uint32_t*)sm;
    __shared__ float wsum[8];

    const int tid  = threadIdx.x;
    const int wid  = tid >> 5;
    const int lane = tid & 31;
    const int tg   = lane & 3;
    const int gq   = lane >> 2;
    const int b0   = blockIdx.x * NB;

    // ---- init mask + norm accumulators ----
    for (int i = tid; i < HW * HW; i += NTHR) {
        int p = i / HW, q = i - p * HW;
        sm[WM_OFF + i] = (float)((baseA[i] == 1) + (momA[q * HW + p] == 1));
    }
    for (int i = tid; i < 256; i += NTHR) sm[SN_OFF + i] = 0.f;

    // ---- staging descriptors (7 slots, fixed across chunks) ----
    uint32_t off[7], dst[7], mo[7]; int sn[7];
    float accn[7];
    #pragma unroll
    for (int j = 0; j < 7; ++j) {
        accn[j] = 0.f;
        int e = tid + j * NTHR;
        if (e < NPAIR) {
            int bb = e / 784;
            int r  = e - bb * 784;
            int t  = r / 392;                 // 0 = A(base), 1 = B(moment)
            int s  = r - t * 392;
            int kp = s / 49;
            int pos = s - kp * 49;
            off[j] = (uint32_t)((b0 + bb) * (CDIM * HW) + kp * 98 + pos)
                   | (t ? 0x80000000u : 0u);
            dst[j] = bb * 2048 + (t ? 1152 + kp * 56 : kp * 72) + pos;
            mo[j]  = t ? 448u : 576u;
            sn[j]  = (bb * 2 + t) * 64 + pos;
        }
    }

    // ---- prologue: stage chunk 0 into buffer 0 ----
    {
        float v0[7], v1[7];
        #pragma unroll
        for (int j = 0; j < 7; ++j)
            if (j < 6 || tid < (NPAIR - 6 * NTHR)) {
                uint32_t o = off[j];
                const float* sp = (o & 0x80000000u) ? momF : baseF;
                const float* p  = sp + (o & 0x7FFFFFFFu);
                v0[j] = __ldg(p); v1[j] = __ldg(p + 49);
            }
        #pragma unroll
        for (int j = 0; j < 7; ++j)
            if (j < 6 || tid < (NPAIR - 6 * NTHR)) {
                uint32_t hi = bf16pack(v0[j], v1[j]);
                float h0 = __uint_as_float(hi << 16);
                float h1 = __uint_as_float(hi & 0xFFFF0000u);
                smw[dst[j]]         = hi;
                smw[dst[j] + mo[j]] = bf16pack(v0[j] - h0, v1[j] - h1);
                accn[j] = fmaf(v0[j], v0[j], fmaf(v1[j], v1[j], accn[j]));
            }
    }

    // ---- main loop ----
    const int bb    = wid >> 2;
    const int mbase = (wid & 3) * 16;
    const int mr    = mbase + gq;
    float acc[7][4];
    #pragma unroll
    for (int nt = 0; nt < 7; ++nt)
        #pragma unroll
        for (int u = 0; u < 4; ++u) acc[nt][u] = 0.f;

    for (int c = 0; c < NCHUNK; ++c) {
        __syncthreads();

        // prefetch LDG for chunk c+1 (hidden under MMAs)
        float v0[7], v1[7];
        if (c + 1 < NCHUNK) {
            #pragma unroll
            for (int j = 0; j < 7; ++j)
                if (j < 6 || tid < (NPAIR - 6 * NTHR)) {
                    uint32_t o = off[j];
                    const float* sp = (o & 0x80000000u) ? momF : baseF;
                    const float* p  = sp + (o & 0x7FFFFFFFu) + (c + 1) * 784;
                    v0[j] = __ldg(p); v1[j] = __ldg(p + 49);
                }
        }

        // ---- MMAs on buffer c&1 ----
        {
            const uint32_t* W  = smw + (c & 1) * BUFW + bb * 2048;
            const uint32_t* Bh = W + 1152;
            uint32_t ah[4], am[4];
            ah[0] = W[tg * 72 + mr];
            ah[1] = W[tg * 72 + mr + 8];
            ah[2] = W[(tg + 4) * 72 + mr];
            ah[3] = W[(tg + 4) * 72 + mr + 8];
            am[0] = W[576 + tg * 72 + mr];
            am[1] = W[576 + tg * 72 + mr + 8];
            am[2] = W[576 + (tg + 4) * 72 + mr];
            am[3] = W[576 + (tg + 4) * 72 + mr + 8];
            #pragma unroll
            for (int nt = 0; nt < 7; ++nt) {
                int o = tg * 56 + nt * 8 + gq;
                uint32_t bh0 = Bh[o],       bh1 = Bh[o + 224];
                uint32_t bm0 = Bh[o + 448], bm1 = Bh[o + 672];
                mma16(acc[nt], ah, bh0, bh1);   // hi * hi
                mma16(acc[nt], ah, bm0, bm1);   // hi * mid
                mma16(acc[nt], am, bh0, bh1);   // mid * hi
            }
        }

        // ---- convert + STS chunk c+1 into the other buffer ----
        if (c + 1 < NCHUNK) {
            uint32_t* dbuf = smw + ((c + 1) & 1) * BUFW;
            #pragma unroll
            for (int j = 0; j < 7; ++j)
                if (j < 6 || tid < (NPAIR - 6 * NTHR)) {
                    uint32_t hi = bf16pack(v0[j], v1[j]);
                    float h0 = __uint_as_float(hi << 16);
                    float h1 = __uint_as_float(hi & 0xFFFF0000u);
                    dbuf[dst[j]]         = hi;
                    dbuf[dst[j] + mo[j]] = bf16pack(v0[j] - h0, v1[j] - h1);
                    accn[j] = fmaf(v0[j], v0[j], fmaf(v1[j], v1[j], accn[j]));
                }
        }
    }

    // ---- flush norm partials ----
    #pragma unroll
    for (int j = 0; j < 7; ++j) {
        int e = tid + j * NTHR;
        if (e < NPAIR) atomicAdd(&sm[SN_OFF + sn[j]], accn[j]);
    }
    __syncthreads();
    if (tid < 4 * HW) {
        int g = tid / HW, p = tid - g * HW;
        sm[SN_OFF + g * 64 + p] = rsqrtf(sm[SN_OFF + g * 64 + p]);
    }
    __syncthreads();

    // ---- epilogue: mask + norms + reduce ----
    {
        const float* invP = sm + SN_OFF + (bb * 2 + 0) * 64;  // base norms
        const float* invQ = sm + SN_OFF + (bb * 2 + 1) * 64;  // moment norms
        const float* wm   = sm + WM_OFF;
        const int r0 = mr;
        const int r1 = r0 + 8;
        const int c0 = tg * 2;
        const bool u0 = r0 < HW, u1 = r1 < HW;
        const float ip0 = u0 ? invP[r0] : 0.f;
        const float ip1 = u1 ? invP[r1] : 0.f;
        float part = 0.f;
        #pragma unroll
        for (int nt = 0; nt < 7; ++nt) {
            int q0 = nt * 8 + c0;
            int q1 = q0 + 1;
            if (q0 < HW) {
                float iq = invQ[q0];
                if (u0) part = fmaf(acc[nt][0], wm[r0 * HW + q0] * ip0 * iq, part);
                if (u1) part = fmaf(acc[nt][2], wm[r1 * HW + q0] * ip1 * iq, part);
            }
            if (q1 < HW) {
                float iq = invQ[q1];
                if (u0) part = fmaf(acc[nt][1], wm[r0 * HW + q1] * ip0 * iq, part);
                if (u1) part = fmaf(acc[nt][3], wm[r1 * HW + q1] * ip1 * iq, part);
            }
        }
        #pragma unroll
        for (int o = 16; o; o >>= 1) part += __shfl_xor_sync(0xFFFFFFFFu, part, o);
        if (lane == 0) wsum[wid] = part;
    }
    __syncthreads();
    if (tid < NB) {
        float t = wsum[tid * 4] + wsum[tid * 4 + 1]
                + wsum[tid * 4 + 2] + wsum[tid * 4 + 3];
        out[b0 + tid] = -t * (1.0f / 2401.0f);
    }
}

extern "C" void kernel_launch(void* const* d_in, const int* in_sizes, int n_in,
                              void* d_out, int out_size) {
    const float* baseF = (const float*)d_in[0];
    const float* momF  = (const float*)d_in[1];
    const int*   baseA = (const int*)d_in[2];
    const int*   momA  = (const int*)d_in[3];
    float* out = (float*)d_out;
    (void)in_sizes; (void)n_in; (void)out_size;

    const int dynBytes = DYN_WORDS * 4;
    cudaFuncSetAttribute(pixpro_bf16, cudaFuncAttributeMaxDynamicSharedMemorySize, dynBytes);
    pixpro_bf16<<<GRID, NTHR, dynBytes>>>(baseF, momF, baseA, momA, out);
}